// round 10
// baseline (speedup 1.0000x reference)
#include <cuda_runtime.h>

#define NB 4
#define NS 2048
#define ND 512
#define NH 8
#define DH 64

__device__ float g_Q[NB*NH*NS*DH];
__device__ float g_K[NB*NH*NS*DH];
__device__ float g_V[NB*NH*NS*DH];
__device__ float g_att[NB*NS*ND];
__device__ float g_x[NB*NS*ND];

typedef unsigned long long u64;

// ---- packed fp32x2 helpers (sm_100+; ptxas won't auto-fuse) ----
__device__ __forceinline__ void fma2(u64 &acc, u64 a, u64 b) {
    asm("fma.rn.f32x2 %0, %1, %2, %0;" : "+l"(acc) : "l"(a), "l"(b));
}
__device__ __forceinline__ void mul2(u64 &d, u64 a) {
    asm("mul.rn.f32x2 %0, %0, %1;" : "+l"(d) : "l"(a));
}
__device__ __forceinline__ u64 dup2(float x) {
    u64 r; asm("mov.b64 %0, {%1, %1};" : "=l"(r) : "f"(x)); return r;
}
__device__ __forceinline__ float2 u2f(u64 u) {
    float2 f; asm("mov.b64 {%0, %1}, %2;" : "=f"(f.x), "=f"(f.y) : "l"(u)); return f;
}

// ============================================================================
// SGEMM C[MxN] = A[MxK] @ B[KxN] + bias. 128x128x16 tile, 8x8 microtile,
// 256 threads, double-buffered, FFMA2 throughout (A staged duplicated).
// QKV=true : scatter into g_Q/g_K/g_V [B,H,S,dh]. QKV=false: A=g_att,
// write g_x = C + bias + g_att (residual).
// ============================================================================
template <int N, int K, bool QKV>
__global__ __launch_bounds__(256, 2) void gemm_kernel(const float* __restrict__ Ain,
                                                      const float* __restrict__ Bw,
                                                      const float* __restrict__ bias) {
    __shared__ float As[2][16][256];   // [buf][kk][2*row] duplicated (32 KB)
    __shared__ float Bs[2][16][128];   // 16 KB

    const float* A = QKV ? Ain : (const float*)g_att;
    const int bm = blockIdx.y * 128;
    const int bn = blockIdx.x * 128;
    const int tid = threadIdx.x;
    const int tx = tid & 15, ty = tid >> 4;

    u64 c[8][4];
#pragma unroll
    for (int i = 0; i < 8; i++)
#pragma unroll
        for (int j = 0; j < 4; j++) c[i][j] = 0ull;

    float4 aR[2], bR[2];
    auto fetch = [&](int t) {
#pragma unroll
        for (int r = 0; r < 2; r++) {
            int idx  = tid + r * 256;
            int arow = idx >> 2, acol = (idx & 3) << 2;
            aR[r] = *(const float4*)&A[(size_t)(bm + arow) * K + t * 16 + acol];
            int brow = idx >> 5, bcol = (idx & 31) << 2;
            bR[r] = *(const float4*)&Bw[(size_t)(t * 16 + brow) * N + bn + bcol];
        }
    };
    auto stage = [&](int buf) {
#pragma unroll
        for (int r = 0; r < 2; r++) {
            int idx  = tid + r * 256;
            int arow = idx >> 2, acol = (idx & 3) << 2;
            float4 v = aR[r];
            *(u64*)&As[buf][acol + 0][2 * arow] = dup2(v.x);
            *(u64*)&As[buf][acol + 1][2 * arow] = dup2(v.y);
            *(u64*)&As[buf][acol + 2][2 * arow] = dup2(v.z);
            *(u64*)&As[buf][acol + 3][2 * arow] = dup2(v.w);
            int brow = idx >> 5, bcol = (idx & 31) << 2;
            *(float4*)&Bs[buf][brow][bcol] = bR[r];
        }
    };

    fetch(0); stage(0); __syncthreads();

    constexpr int NT = K / 16;
    int buf = 0;
    for (int t = 0; t < NT; t++) {
        if (t + 1 < NT) fetch(t + 1);
#pragma unroll
        for (int kk = 0; kk < 16; kk++) {
            ulonglong2 a01 = *(const ulonglong2*)&As[buf][kk][16 * ty];
            ulonglong2 a23 = *(const ulonglong2*)&As[buf][kk][16 * ty + 4];
            ulonglong2 a45 = *(const ulonglong2*)&As[buf][kk][16 * ty + 8];
            ulonglong2 a67 = *(const ulonglong2*)&As[buf][kk][16 * ty + 12];
            ulonglong2 b01 = *(const ulonglong2*)&Bs[buf][kk][8 * tx];
            ulonglong2 b23 = *(const ulonglong2*)&Bs[buf][kk][8 * tx + 4];
            u64 a[8] = {a01.x, a01.y, a23.x, a23.y, a45.x, a45.y, a67.x, a67.y};
            u64 b[4] = {b01.x, b01.y, b23.x, b23.y};
#pragma unroll
            for (int i = 0; i < 8; i++)
#pragma unroll
                for (int j = 0; j < 4; j++) fma2(c[i][j], a[i], b[j]);
        }
        if (t + 1 < NT) stage(buf ^ 1);
        __syncthreads();
        buf ^= 1;
    }

#pragma unroll
    for (int i = 0; i < 8; i++) {
        int m = bm + ty * 8 + i;
#pragma unroll
        for (int jj = 0; jj < 2; jj++) {
            int n = bn + tx * 8 + jj * 4;
            float2 lo = u2f(c[i][2 * jj]);
            float2 hi = u2f(c[i][2 * jj + 1]);
            float4 bv = *(const float4*)&bias[n];
            float4 val = make_float4(lo.x + bv.x, lo.y + bv.y, hi.x + bv.z, hi.y + bv.w);
            if (QKV) {
                int bb = m >> 11, s = m & 2047;
                int seg = n >> 9, hh = (n & 511) >> 6, dd = n & 63;
                float* dst = (seg == 0) ? g_Q : (seg == 1 ? g_K : g_V);
                *(float4*)&dst[(((size_t)bb * NH + hh) * NS + s) * DH + dd] = val;
            } else {
                float4 rv = *(const float4*)&g_att[(size_t)m * ND + n];
                val.x += rv.x; val.y += rv.y; val.z += rv.z; val.w += rv.w;
                *(float4*)&g_x[(size_t)m * ND + n] = val;
            }
        }
    }
}

// ============================================================================
// Flash attention fp32, unscaled scores, key mask, online softmax.
// Grid 1024 = B*H*(S/64); block 256 = 8 warps; warp w owns query rows w*8..+8.
// Scores: lane owns key pair (2l,2l+1). PV: lane owns dh pair (2l,2l+1).
// All inner math FFMA2; scalar operands (q, p) live duplicated in smem.
// ============================================================================
#define ATT_SMEM 99072

__global__ __launch_bounds__(256, 2) void attn_kernel(const int* __restrict__ mask) {
    extern __shared__ float sm[];
    float* Qd  = sm;                          // [64][128] q duplicated (32 KB)
    float* Kt  = sm + 8192;                   // [64 d][66] transposed (16.5 KB)
    float* Vs  = sm + 8192 + 4224;            // [64 key][64 d] (16 KB)
    float* Psd = sm + 8192 + 4224 + 4096;     // [64 row][128] p duplicated (32 KB)
    int*   ms  = (int*)(sm + 8192 + 4224 + 4096 + 8192);

    const int bh = blockIdx.x >> 5;           // b*8 + h
    const int qt = blockIdx.x & 31;
    const int b = bh >> 3, h = bh & 7;
    const float* Qb = g_Q + ((size_t)bh * NS + qt * 64) * DH;
    const float* Kb = g_K + (size_t)bh * NS * DH;
    const float* Vb = g_V + (size_t)bh * NS * DH;
    const int*   mb = mask + b * NS;

    const int tid = threadIdx.x, lane = tid & 31, w = tid >> 5;
    const int row0 = w * 8;

    // stage Q duplicated: Qd[row][2d],Qd[row][2d+1] = Q[row][d]
#pragma unroll
    for (int r = 0; r < 4; r++) {
        int idx = tid + r * 256;              // 1024 float4s
        int row = idx >> 4, c4 = (idx & 15) << 2;
        float4 q = ((const float4*)Qb)[idx];
        float* dst = &Qd[row * 128 + c4 * 2];
        ((float4*)dst)[0] = make_float4(q.x, q.x, q.y, q.y);
        ((float4*)dst)[1] = make_float4(q.z, q.z, q.w, q.w);
    }

    u64 o[8];
    float mi[8], li[8];
#pragma unroll
    for (int r = 0; r < 8; r++) { o[r] = 0ull; mi[r] = -1e30f; li[r] = 0.f; }

    for (int kt = 0; kt < 32; kt++) {
        __syncthreads();                      // prev PV done before restage
        const float4* Kg = (const float4*)(Kb + kt * 4096);
        const float4* Vg = (const float4*)(Vb + kt * 4096);
#pragma unroll
        for (int r = 0; r < 4; r++) {
            int idx = tid + r * 256;
            int key = idx >> 4, d4 = (idx & 15) << 2;
            float4 kv = Kg[idx];
            Kt[(d4 + 0) * 66 + key] = kv.x;
            Kt[(d4 + 1) * 66 + key] = kv.y;
            Kt[(d4 + 2) * 66 + key] = kv.z;
            Kt[(d4 + 3) * 66 + key] = kv.w;
            ((float4*)Vs)[idx] = Vg[idx];
        }
        if (tid < 64) ms[tid] = mb[kt * 64 + tid];
        __syncthreads();

        // ---- scores: s[r] = packed (score[2l], score[2l+1]) ----
        u64 s[8];
#pragma unroll
        for (int r = 0; r < 8; r++) s[r] = 0ull;
#pragma unroll 4
        for (int d4 = 0; d4 < 64; d4 += 4) {
            u64 k0 = *(const u64*)&Kt[(d4 + 0) * 66 + 2 * lane];
            u64 k1 = *(const u64*)&Kt[(d4 + 1) * 66 + 2 * lane];
            u64 k2 = *(const u64*)&Kt[(d4 + 2) * 66 + 2 * lane];
            u64 k3 = *(const u64*)&Kt[(d4 + 3) * 66 + 2 * lane];
#pragma unroll
            for (int r = 0; r < 8; r++) {
                const ulonglong2* qp = (const ulonglong2*)&Qd[(row0 + r) * 128 + 2 * d4];
                ulonglong2 qa = qp[0], qb2 = qp[1];
                fma2(s[r], k0, qa.x);
                fma2(s[r], k1, qa.y);
                fma2(s[r], k2, qb2.x);
                fma2(s[r], k3, qb2.y);
            }
        }

        // ---- online softmax ----
        int m0 = ms[2 * lane], m1 = ms[2 * lane + 1];
#pragma unroll
        for (int r = 0; r < 8; r++) {
            float2 v = u2f(s[r]);
            if (!m0) v.x = -1e30f;
            if (!m1) v.y = -1e30f;
            float mx = fmaxf(v.x, v.y);
#pragma unroll
            for (int off = 16; off; off >>= 1)
                mx = fmaxf(mx, __shfl_xor_sync(0xFFFFFFFFu, mx, off));
            float mnew = fmaxf(mi[r], mx);
            float p0 = __expf(v.x - mnew);
            float p1 = __expf(v.y - mnew);
            float ls = p0 + p1;
#pragma unroll
            for (int off = 16; off; off >>= 1)
                ls += __shfl_xor_sync(0xFFFFFFFFu, ls, off);
            float corr = __expf(mi[r] - mnew);
            li[r] = li[r] * corr + ls;
            mi[r] = mnew;
            mul2(o[r], dup2(corr));
            *(float4*)&Psd[(row0 + r) * 128 + 4 * lane] = make_float4(p0, p0, p1, p1);
        }
        __syncwarp();

        // ---- PV: o[r] += sum_key p(row,key) * V[key][dh pair] ----
#pragma unroll 4
        for (int k4 = 0; k4 < 64; k4 += 4) {
            u64 v0 = *(const u64*)&Vs[(k4 + 0) * 64 + 2 * lane];
            u64 v1 = *(const u64*)&Vs[(k4 + 1) * 64 + 2 * lane];
            u64 v2 = *(const u64*)&Vs[(k4 + 2) * 64 + 2 * lane];
            u64 v3 = *(const u64*)&Vs[(k4 + 3) * 64 + 2 * lane];
#pragma unroll
            for (int r = 0; r < 8; r++) {
                const ulonglong2* pp = (const ulonglong2*)&Psd[(row0 + r) * 128 + 2 * k4];
                ulonglong2 pa = pp[0], pb = pp[1];
                fma2(o[r], v0, pa.x);
                fma2(o[r], v1, pa.y);
                fma2(o[r], v2, pb.x);
                fma2(o[r], v3, pb.y);
            }
        }
    }

    // normalize and write to g_att [B,S,D]
#pragma unroll
    for (int r = 0; r < 8; r++) {
        mul2(o[r], dup2(1.f / li[r]));
        size_t sg = (size_t)qt * 64 + row0 + r;
        size_t off = ((size_t)b * NS + sg) * ND + h * DH + 2 * lane;
        *(u64*)&g_att[off] = o[r];
    }
}

// ============================================================================
// LayerNorm over last dim (512). 1 block (128 thr) per row, float4 per thread.
// ============================================================================
__global__ void ln_kernel(const float* __restrict__ gamma, const float* __restrict__ beta,
                          float* __restrict__ out) {
    __shared__ float red[8];
    int row = blockIdx.x, t = threadIdx.x;
    float4 xv = ((const float4*)&g_x[(size_t)row * ND])[t];
    float s = xv.x + xv.y + xv.z + xv.w;
    float q = xv.x * xv.x + xv.y * xv.y + xv.z * xv.z + xv.w * xv.w;
#pragma unroll
    for (int off = 16; off; off >>= 1) {
        s += __shfl_xor_sync(0xFFFFFFFFu, s, off);
        q += __shfl_xor_sync(0xFFFFFFFFu, q, off);
    }
    if ((t & 31) == 0) { red[t >> 5] = s; red[4 + (t >> 5)] = q; }
    __syncthreads();
    s = red[0] + red[1] + red[2] + red[3];
    q = red[4] + red[5] + red[6] + red[7];
    float mu = s * (1.f / 512.f);
    float var = q * (1.f / 512.f) - mu * mu;
    float rs = rsqrtf(var + 1e-5f);
    float4 g = ((const float4*)gamma)[t];
    float4 be = ((const float4*)beta)[t];
    float4 r;
    r.x = (xv.x - mu) * rs * g.x + be.x;
    r.y = (xv.y - mu) * rs * g.y + be.y;
    r.z = (xv.z - mu) * rs * g.z + be.z;
    r.w = (xv.w - mu) * rs * g.w + be.w;
    ((float4*)&out[(size_t)row * ND])[t] = r;
}

extern "C" void kernel_launch(void* const* d_in, const int* in_sizes, int n_in,
                              void* d_out, int out_size) {
    const float* x_in  = (const float*)d_in[0];   // [4,2048,512]
    const int*   mask  = (const int*)d_in[1];     // [4,2048]
    const float* W_qkv = (const float*)d_in[2];   // [512,1536]
    const float* b_qkv = (const float*)d_in[3];   // [1536]
    const float* W_o   = (const float*)d_in[4];   // [512,512]
    const float* b_o   = (const float*)d_in[5];   // [512]
    const float* gamma = (const float*)d_in[6];   // [512]
    const float* beta  = (const float*)d_in[7];   // [512]
    float* out = (float*)d_out;

    cudaFuncSetAttribute(attn_kernel, cudaFuncAttributeMaxDynamicSharedMemorySize, ATT_SMEM);

    // 1) QKV projection: [8192,512] @ [512,1536] + bias -> Q/K/V [B,H,S,dh]
    gemm_kernel<1536, 512, true><<<dim3(12, 64), 256>>>(x_in, W_qkv, b_qkv);
    // 2) attention -> g_att [B,S,D]
    attn_kernel<<<1024, 256, ATT_SMEM>>>(mask);
    // 3) output projection + bias + residual -> g_x
    gemm_kernel<512, 512, false><<<dim3(4, 64), 256>>>(nullptr, W_o, b_o);
    // 4) layernorm -> out
    ln_kernel<<<NB * NS, 128>>>(gamma, beta, out);
}